// round 1
// baseline (speedup 1.0000x reference)
#include <cuda_runtime.h>
#include <math.h>
#include <stdint.h>

#define EMB   1024
#define DFF   4096
#define HEADS 16
#define DH    64
#define BATCH 2
#define SEQ   2048
#define TOK   (BATCH*SEQ)   // 4096 rows

// ---------------- scratch (static __device__ — no allocations) ----------------
__device__ float g_h   [(size_t)TOK*EMB];                     // LN1 output
__device__ float g_q   [(size_t)TOK*EMB];
__device__ float g_k   [(size_t)TOK*EMB];
__device__ float g_v   [(size_t)TOK*EMB];
__device__ float g_S   [(size_t)BATCH*HEADS*SEQ*SEQ];         // 512 MB score buffer
__device__ float g_attn[(size_t)TOK*EMB];                     // attn out + residual
__device__ float g_h2  [(size_t)TOK*EMB];                     // LN2 output
__device__ float g_ff  [(size_t)TOK*DFF];                     // FFN hidden

// ---------------- LayerNorm: one block per row of 1024 ----------------
__global__ void ln_kernel(const float* __restrict__ x,
                          const float* __restrict__ gamma,
                          const float* __restrict__ beta,
                          float* __restrict__ out) {
    int row = blockIdx.x;
    const float* xr = x + (size_t)row * EMB;
    float*       orw = out + (size_t)row * EMB;
    int tid = threadIdx.x;            // 256 threads, 4 elems each
    float v[4];
    float s = 0.f, s2 = 0.f;
#pragma unroll
    for (int i = 0; i < 4; i++) {
        float t = xr[tid + i * 256];
        v[i] = t; s += t; s2 += t * t;
    }
#pragma unroll
    for (int o = 16; o > 0; o >>= 1) {
        s  += __shfl_down_sync(0xFFFFFFFFu, s,  o);
        s2 += __shfl_down_sync(0xFFFFFFFFu, s2, o);
    }
    __shared__ float rs[8], rs2[8];
    __shared__ float mu_s, rstd_s;
    int wid = tid >> 5, lane = tid & 31;
    if (lane == 0) { rs[wid] = s; rs2[wid] = s2; }
    __syncthreads();
    if (wid == 0) {
        float a  = (lane < 8) ? rs[lane]  : 0.f;
        float a2 = (lane < 8) ? rs2[lane] : 0.f;
#pragma unroll
        for (int o = 4; o > 0; o >>= 1) {
            a  += __shfl_down_sync(0xFFFFFFFFu, a,  o);
            a2 += __shfl_down_sync(0xFFFFFFFFu, a2, o);
        }
        if (lane == 0) {
            float mu  = a * (1.0f / EMB);
            float var = a2 * (1.0f / EMB) - mu * mu;
            mu_s = mu;
            rstd_s = rsqrtf(var + 1e-6f);
        }
    }
    __syncthreads();
    float mu = mu_s, rstd = rstd_s;
#pragma unroll
    for (int i = 0; i < 4; i++) {
        int c = tid + i * 256;
        orw[c] = (v[i] - mu) * rstd * gamma[c] + beta[c];
    }
}

// ---------------- generic tiled fp32 GEMM ----------------
// C[M,N] = A[M,K] @ B  (+bias)(+gelu)(+resid)
// transB=0: B is K x N (ldb). transB=1: B is N x K (ldb) -> C = A @ B^T.
// Batched over blockIdx.z via per-(batch,head) offsets: z = zb*16 + zh.
// All dims assumed multiples of tile sizes (true for this problem).
__global__ void __launch_bounds__(256)
gemm_kernel(const float* __restrict__ A, int lda, long ofsAb, long ofsAh,
            const float* __restrict__ B, int ldb, long ofsBb, long ofsBh, int transB,
            const float* __restrict__ bias,
            const float* __restrict__ resid, int ldr, long ofsRb, long ofsRh,
            float* __restrict__ C, int ldc, long ofsCb, long ofsCh,
            int K, int act_gelu) {
    int z = blockIdx.z;
    int zb = z >> 4, zh = z & 15;
    A += (size_t)zb * ofsAb + (size_t)zh * ofsAh;
    B += (size_t)zb * ofsBb + (size_t)zh * ofsBh;
    C += (size_t)zb * ofsCb + (size_t)zh * ofsCh;
    if (resid) resid += (size_t)zb * ofsRb + (size_t)zh * ofsRh;

    __shared__ float As[16][64];
    __shared__ float Bs[16][64];

    int tid = threadIdx.x;
    int tx = tid & 15, ty = tid >> 4;

    float acc[4][4];
#pragma unroll
    for (int i = 0; i < 4; i++)
#pragma unroll
        for (int j = 0; j < 4; j++) acc[i][j] = 0.f;

    // A-load mapping: 64 rows x 16 k, each thread a float4 along K
    int arow = tid >> 2;
    int akc  = (tid & 3) * 4;
    const float* Aptr = A + (size_t)(blockIdx.y * 64 + arow) * lda + akc;

    for (int k0 = 0; k0 < K; k0 += 16) {
        float4 av = *(const float4*)(Aptr);
        Aptr += 16;
        As[akc + 0][arow] = av.x;
        As[akc + 1][arow] = av.y;
        As[akc + 2][arow] = av.z;
        As[akc + 3][arow] = av.w;

        if (!transB) {
            int brow = tid >> 4;          // 0..15
            int bcol = (tid & 15) * 4;    // 0..60
            float4 bv = *(const float4*)(B + (size_t)(k0 + brow) * ldb
                                           + (size_t)blockIdx.x * 64 + bcol);
            *(float4*)&Bs[brow][bcol] = bv;
        } else {
            int bn  = tid >> 2;           // 0..63
            int bkc = (tid & 3) * 4;
            float4 bv = *(const float4*)(B + (size_t)(blockIdx.x * 64 + bn) * ldb
                                           + k0 + bkc);
            Bs[bkc + 0][bn] = bv.x;
            Bs[bkc + 1][bn] = bv.y;
            Bs[bkc + 2][bn] = bv.z;
            Bs[bkc + 3][bn] = bv.w;
        }
        __syncthreads();

#pragma unroll
        for (int kk = 0; kk < 16; kk++) {
            float4 a4 = *(const float4*)&As[kk][ty * 4];
            float4 b4 = *(const float4*)&Bs[kk][tx * 4];
            float ar[4] = {a4.x, a4.y, a4.z, a4.w};
            float br[4] = {b4.x, b4.y, b4.z, b4.w};
#pragma unroll
            for (int i = 0; i < 4; i++)
#pragma unroll
                for (int j = 0; j < 4; j++)
                    acc[i][j] = fmaf(ar[i], br[j], acc[i][j]);
        }
        __syncthreads();
    }

    int crow0 = blockIdx.y * 64 + ty * 4;
    int ccol0 = blockIdx.x * 64 + tx * 4;
#pragma unroll
    for (int i = 0; i < 4; i++) {
#pragma unroll
        for (int j = 0; j < 4; j++) {
            float c = acc[i][j];
            if (bias) c += bias[ccol0 + j];
            if (act_gelu) c = 0.5f * c * (1.0f + erff(c * 0.70710678118654752f));
            if (resid) c += resid[(size_t)(crow0 + i) * ldr + ccol0 + j];
            C[(size_t)(crow0 + i) * ldc + ccol0 + j] = c;
        }
    }
}

// ---------------- row softmax over SEQ=2048, one block per row ----------------
__global__ void softmax_kernel(float* __restrict__ S) {
    float* p = S + (size_t)blockIdx.x * SEQ;
    int tid = threadIdx.x;                 // 256 threads, 8 elems each
    float v[8];
    float m = -1e30f;
#pragma unroll
    for (int i = 0; i < 8; i++) {
        v[i] = p[tid + i * 256];
        m = fmaxf(m, v[i]);
    }
#pragma unroll
    for (int o = 16; o > 0; o >>= 1)
        m = fmaxf(m, __shfl_down_sync(0xFFFFFFFFu, m, o));
    __shared__ float rm[8];
    __shared__ float m_s, s_s;
    int wid = tid >> 5, lane = tid & 31;
    if (lane == 0) rm[wid] = m;
    __syncthreads();
    if (wid == 0) {
        float a = (lane < 8) ? rm[lane] : -1e30f;
#pragma unroll
        for (int o = 4; o > 0; o >>= 1)
            a = fmaxf(a, __shfl_down_sync(0xFFFFFFFFu, a, o));
        if (lane == 0) m_s = a;
    }
    __syncthreads();
    m = m_s;
    float s = 0.f;
#pragma unroll
    for (int i = 0; i < 8; i++) {
        v[i] = __expf(v[i] - m);
        s += v[i];
    }
#pragma unroll
    for (int o = 16; o > 0; o >>= 1)
        s += __shfl_down_sync(0xFFFFFFFFu, s, o);
    if (lane == 0) rm[wid] = s;
    __syncthreads();
    if (wid == 0) {
        float a = (lane < 8) ? rm[lane] : 0.f;
#pragma unroll
        for (int o = 4; o > 0; o >>= 1)
            a += __shfl_down_sync(0xFFFFFFFFu, a, o);
        if (lane == 0) s_s = a;
    }
    __syncthreads();
    float inv = 1.0f / s_s;
#pragma unroll
    for (int i = 0; i < 8; i++)
        p[tid + i * 256] = v[i] * inv;
}

// ---------------- launch ----------------
extern "C" void kernel_launch(void* const* d_in, const int* in_sizes, int n_in,
                              void* d_out, int out_size) {
    const float* x   = (const float*)d_in[0];
    const float* Wq  = (const float*)d_in[1];
    const float* bq  = (const float*)d_in[2];
    const float* Wk  = (const float*)d_in[3];
    const float* bk  = (const float*)d_in[4];
    const float* Wv  = (const float*)d_in[5];
    const float* bv  = (const float*)d_in[6];
    const float* g1  = (const float*)d_in[7];
    const float* be1 = (const float*)d_in[8];
    const float* g2  = (const float*)d_in[9];
    const float* be2 = (const float*)d_in[10];
    const float* W1  = (const float*)d_in[11];
    const float* b1  = (const float*)d_in[12];
    const float* W2  = (const float*)d_in[13];
    const float* b2  = (const float*)d_in[14];
    float* out = (float*)d_out;

    float *h, *q, *k, *v, *S, *attn, *h2, *ff;
    cudaGetSymbolAddress((void**)&h,    g_h);
    cudaGetSymbolAddress((void**)&q,    g_q);
    cudaGetSymbolAddress((void**)&k,    g_k);
    cudaGetSymbolAddress((void**)&v,    g_v);
    cudaGetSymbolAddress((void**)&S,    g_S);
    cudaGetSymbolAddress((void**)&attn, g_attn);
    cudaGetSymbolAddress((void**)&h2,   g_h2);
    cudaGetSymbolAddress((void**)&ff,   g_ff);

    // 1) LN1
    ln_kernel<<<TOK, 256>>>(x, g1, be1, h);

    // 2) Q,K,V projections: [4096,1024] = h @ W + b
    {
        dim3 grid(EMB / 64, TOK / 64, 1);
        gemm_kernel<<<grid, 256>>>(h, EMB, 0, 0,
                                   Wq, EMB, 0, 0, 0,
                                   bq, nullptr, 0, 0, 0,
                                   q, EMB, 0, 0, EMB, 0);
        gemm_kernel<<<grid, 256>>>(h, EMB, 0, 0,
                                   Wk, EMB, 0, 0, 0,
                                   bk, nullptr, 0, 0, 0,
                                   k, EMB, 0, 0, EMB, 0);
        gemm_kernel<<<grid, 256>>>(h, EMB, 0, 0,
                                   Wv, EMB, 0, 0, 0,
                                   bv, nullptr, 0, 0, 0,
                                   v, EMB, 0, 0, EMB, 0);
    }

    // 3) scores: per (b,h), S = q_bh @ k_bh^T  [2048 x 2048], K=64 (no scaling)
    {
        dim3 grid(SEQ / 64, SEQ / 64, BATCH * HEADS);
        long tokOfs = (long)SEQ * EMB;  // batch stride in q/k/v
        long sOfsH  = (long)SEQ * SEQ;
        gemm_kernel<<<grid, 256>>>(q, EMB, tokOfs, DH,
                                   k, EMB, tokOfs, DH, 1,
                                   nullptr, nullptr, 0, 0, 0,
                                   S, SEQ, sOfsH * HEADS, sOfsH,
                                   DH, 0);
    }

    // 4) softmax over each score row
    softmax_kernel<<<BATCH * HEADS * SEQ, 256>>>(S);

    // 5) attn_out = P @ v_bh  [2048 x 64], K=2048; fuse "+ x" residual
    {
        dim3 grid(1, SEQ / 64, BATCH * HEADS);
        long tokOfs = (long)SEQ * EMB;
        long sOfsH  = (long)SEQ * SEQ;
        gemm_kernel<<<grid, 256>>>(S, SEQ, sOfsH * HEADS, sOfsH,
                                   v, EMB, tokOfs, DH, 0,
                                   nullptr,
                                   x, EMB, tokOfs, DH,
                                   attn, EMB, tokOfs, DH,
                                   SEQ, 0);
    }

    // 6) LN2
    ln_kernel<<<TOK, 256>>>(attn, g2, be2, h2);

    // 7) FFN1: [4096,4096] = h2 @ W1 + b1, exact GELU
    {
        dim3 grid(DFF / 64, TOK / 64, 1);
        gemm_kernel<<<grid, 256>>>(h2, EMB, 0, 0,
                                   W1, DFF, 0, 0, 0,
                                   b1, nullptr, 0, 0, 0,
                                   ff, DFF, 0, 0, EMB, 1);
    }

    // 8) FFN2: out = ff @ W2 + b2 + attn  (residual), write d_out
    {
        dim3 grid(EMB / 64, TOK / 64, 1);
        gemm_kernel<<<grid, 256>>>(ff, DFF, 0, 0,
                                   W2, EMB, 0, 0, 0,
                                   b2,
                                   attn, EMB, 0, 0,
                                   out, EMB, 0, 0, DFF, 0);
    }
}

// round 3
// speedup vs baseline: 3.0699x; 3.0699x over previous
#include <cuda_runtime.h>
#include <cuda_bf16.h>
#include <math.h>
#include <stdint.h>

#define EMB   1024
#define DFF   4096
#define HEADS 16
#define DH    64
#define BATCH 2
#define SEQ   2048
#define TOK   (BATCH*SEQ)

typedef __nv_bfloat16 bf16;

// ============================ scratch (static, no allocs) ============================
__device__ __align__(1024) bf16 g_hhi [(size_t)TOK*EMB];
__device__ __align__(1024) bf16 g_hlo [(size_t)TOK*EMB];
__device__ __align__(1024) bf16 g_wqhi[(size_t)EMB*EMB];
__device__ __align__(1024) bf16 g_wqlo[(size_t)EMB*EMB];
__device__ __align__(1024) bf16 g_wkhi[(size_t)EMB*EMB];
__device__ __align__(1024) bf16 g_wklo[(size_t)EMB*EMB];
__device__ __align__(1024) bf16 g_wvhi[(size_t)EMB*EMB];
__device__ __align__(1024) bf16 g_wvlo[(size_t)EMB*EMB];
__device__ __align__(1024) bf16 g_w1hi[(size_t)DFF*EMB];   // [N=4096,K=1024]
__device__ __align__(1024) bf16 g_w1lo[(size_t)DFF*EMB];
__device__ __align__(1024) bf16 g_w2hi[(size_t)EMB*DFF];   // [N=1024,K=4096]
__device__ __align__(1024) bf16 g_w2lo[(size_t)EMB*DFF];
__device__ __align__(1024) bf16 g_qhi [(size_t)TOK*EMB];
__device__ __align__(1024) bf16 g_qlo [(size_t)TOK*EMB];
__device__ __align__(1024) bf16 g_khi [(size_t)TOK*EMB];
__device__ __align__(1024) bf16 g_klo [(size_t)TOK*EMB];
__device__ __align__(1024) bf16 g_vhi [(size_t)TOK*EMB];
__device__ __align__(1024) bf16 g_vlo [(size_t)TOK*EMB];
__device__ __align__(1024) float g_S  [(size_t)BATCH*HEADS*SEQ*SEQ]; // 512MB
__device__ __align__(1024) bf16 g_Phi [(size_t)BATCH*HEADS*SEQ*SEQ];
__device__ __align__(1024) bf16 g_Plo [(size_t)BATCH*HEADS*SEQ*SEQ];
__device__ __align__(1024) float g_attn[(size_t)TOK*EMB];
__device__ __align__(1024) bf16 g_h2hi[(size_t)TOK*EMB];
__device__ __align__(1024) bf16 g_h2lo[(size_t)TOK*EMB];
__device__ __align__(1024) bf16 g_ffhi[(size_t)TOK*DFF];
__device__ __align__(1024) bf16 g_fflo[(size_t)TOK*DFF];

// ============================ PTX helpers ============================
__device__ __forceinline__ uint32_t smem_u32(const void* p) {
    uint32_t a;
    asm("{ .reg .u64 t; cvta.to.shared.u64 t, %1; cvt.u32.u64 %0, t; }" : "=r"(a) : "l"(p));
    return a;
}
__device__ __forceinline__ void cpasync16(uint32_t dst, const void* src) {
    asm volatile("cp.async.cg.shared.global [%0], [%1], 16;\n" :: "r"(dst), "l"(src));
}
#define CP_COMMIT()  asm volatile("cp.async.commit_group;\n" ::: "memory")
#define CP_WAIT0()   asm volatile("cp.async.wait_group 0;\n" ::: "memory")
#define CP_WAIT1()   asm volatile("cp.async.wait_group 1;\n" ::: "memory")

__device__ __forceinline__ void ldm_x4(uint32_t* r, uint32_t addr) {
    asm volatile("ldmatrix.sync.aligned.m8n8.x4.shared.b16 {%0,%1,%2,%3}, [%4];"
                 : "=r"(r[0]), "=r"(r[1]), "=r"(r[2]), "=r"(r[3]) : "r"(addr));
}
__device__ __forceinline__ void ldm_x4_t(uint32_t* r, uint32_t addr) {
    asm volatile("ldmatrix.sync.aligned.m8n8.x4.trans.shared.b16 {%0,%1,%2,%3}, [%4];"
                 : "=r"(r[0]), "=r"(r[1]), "=r"(r[2]), "=r"(r[3]) : "r"(addr));
}
__device__ __forceinline__ void mma16816(float* d, const uint32_t* a, const uint32_t* b) {
    asm volatile(
        "mma.sync.aligned.m16n8k16.row.col.f32.bf16.bf16.f32 "
        "{%0,%1,%2,%3}, {%4,%5,%6,%7}, {%8,%9}, {%0,%1,%2,%3};"
        : "+f"(d[0]), "+f"(d[1]), "+f"(d[2]), "+f"(d[3])
        : "r"(a[0]), "r"(a[1]), "r"(a[2]), "r"(a[3]), "r"(b[0]), "r"(b[1]));
}

#define SWZ(o) ((o) ^ (((o) >> 3) & 0x70))

__device__ __forceinline__ void split2(float v, bf16& hi, bf16& lo) {
    hi = __float2bfloat16(v);
    lo = __float2bfloat16(v - __bfloat162float(hi));
}

// ============================ split-precision mma.sync GEMM ============================
// C[M,N] = (Ahi+Alo)[M,K] @ B^T where:
//   TRANSB=false: B given as [N,K] K-major (row = n, contiguous k)
//   TRANSB=true : B given as [K,N] N-major (row = k, contiguous n); TN must be 64
// CTA tile 128 x TN, KC=64, double-buffered cp.async, 8 warps of 64 x (TN/4).
// modes: 0 fp32(+bias); 1 split bf16(+bias); 3 bias+gelu->split; 4 (+bias)+resid->fp32
template<int TN, bool TRANSB>
__global__ void __launch_bounds__(256)
gemmw_kernel(const bf16* __restrict__ Ahi, const bf16* __restrict__ Alo,
             int lda, long ofsAb, long ofsAh,
             const bf16* __restrict__ Bhi, const bf16* __restrict__ Blo,
             int ldb, long ofsBb, long ofsBh,
             const float* __restrict__ bias,
             const float* __restrict__ resid, int ldr, long ofsRb, long ofsRh,
             void* outHi, void* outLo, int ldc, long ofsCb, long ofsCh,
             int K, int mode) {
    static_assert(!TRANSB || TN == 64, "trans-B tile assumes 128B rows");
    constexpr int KC      = 64;
    constexpr int ABYTES  = 128 * 128;                       // 128 rows x 128B
    constexpr int BBYTES  = TRANSB ? (64 * TN * 2) : (TN * 128);
    constexpr int STAGE   = 2 * ABYTES + 2 * BBYTES;
    constexpr int WN      = TN / 4;                          // warp n-span
    constexpr int NJ      = WN / 16;                         // n16 blocks per warp

    extern __shared__ char smem[];
    uint32_t sb = smem_u32(smem);

    int tid = threadIdx.x;
    int wid = tid >> 5, lane = tid & 31;
    int wm = wid >> 2, wn = wid & 3;                          // 2 x 4 warp grid
    int sub = lane >> 3, r = lane & 7;

    int z  = blockIdx.z;
    int zb = z >> 4, zh = z & 15;
    Ahi += (size_t)zb * ofsAb + (size_t)zh * ofsAh;
    Alo += (size_t)zb * ofsAb + (size_t)zh * ofsAh;
    Bhi += (size_t)zb * ofsBb + (size_t)zh * ofsBh;
    Blo += (size_t)zb * ofsBb + (size_t)zh * ofsBh;
    if (resid) resid += (size_t)zb * ofsRb + (size_t)zh * ofsRh;

    int m0 = blockIdx.y * 128;
    int n0 = blockIdx.x * TN;

    float acc[4][NJ * 2][4];
#pragma unroll
    for (int i = 0; i < 4; i++)
#pragma unroll
        for (int j = 0; j < NJ * 2; j++)
#pragma unroll
            for (int t = 0; t < 4; t++) acc[i][j][t] = 0.f;

    const int nIter = K / KC;

    auto load_stage = [&](int it, int s) {
        int k0 = it * KC;
        uint32_t AhB = sb + s * STAGE;
        uint32_t AlB = AhB + ABYTES;
        uint32_t BhB = AlB + ABYTES;
        uint32_t BlB = BhB + BBYTES;
#pragma unroll
        for (int t = 0; t < 4; t++) {                          // A: 1024 16B pairs
            int idx = tid + t * 256;
            int row = idx >> 3, seg = idx & 7;
            size_t go = (size_t)(m0 + row) * lda + k0 + seg * 8;
            uint32_t so = SWZ(row * 128 + seg * 16);
            cpasync16(AhB + so, Ahi + go);
            cpasync16(AlB + so, Alo + go);
        }
        if (!TRANSB) {
            constexpr int BT = (TN * 8) / 256;
#pragma unroll
            for (int t = 0; t < BT; t++) {
                int idx = tid + t * 256;
                int row = idx >> 3, seg = idx & 7;
                size_t go = (size_t)(n0 + row) * ldb + k0 + seg * 8;
                uint32_t so = SWZ(row * 128 + seg * 16);
                cpasync16(BhB + so, Bhi + go);
                cpasync16(BlB + so, Blo + go);
            }
        } else {                                               // [KC=64][128B]
#pragma unroll
            for (int t = 0; t < 2; t++) {
                int idx = tid + t * 256;
                int row = idx >> 3, seg = idx & 7;
                size_t go = (size_t)(k0 + row) * ldb + n0 + seg * 8;
                uint32_t so = SWZ(row * 128 + seg * 16);
                cpasync16(BhB + so, Bhi + go);
                cpasync16(BlB + so, Blo + go);
            }
        }
        CP_COMMIT();
    };

    load_stage(0, 0);

    for (int it = 0; it < nIter; it++) {
        int s = it & 1;
        if (it + 1 < nIter) {
            load_stage(it + 1, s ^ 1);
            CP_WAIT1();
        } else {
            CP_WAIT0();
        }
        __syncthreads();

        uint32_t AhB = sb + s * STAGE;
        uint32_t AlB = AhB + ABYTES;
        uint32_t BhB = AlB + ABYTES;
        uint32_t BlB = BhB + BBYTES;

#pragma unroll
        for (int ks = 0; ks < 4; ks++) {
            uint32_t ah[4][4], al[4][4];
#pragma unroll
            for (int mi = 0; mi < 4; mi++) {
                int row = wm * 64 + mi * 16 + (sub & 1) * 8 + r;
                int kb  = ks * 32 + (sub >> 1) * 16;
                uint32_t so = SWZ(row * 128 + kb);
                ldm_x4(ah[mi], AhB + so);
                ldm_x4(al[mi], AlB + so);
            }
            uint32_t bh[NJ][4], bl[NJ][4];
#pragma unroll
            for (int j = 0; j < NJ; j++) {
                if (!TRANSB) {
                    int nrow = wn * WN + j * 16 + (sub >> 1) * 8 + r;
                    int kb   = ks * 32 + (sub & 1) * 16;
                    uint32_t so = SWZ(nrow * 128 + kb);
                    ldm_x4(bh[j], BhB + so);
                    ldm_x4(bl[j], BlB + so);
                } else {
                    int krow = ks * 16 + (sub & 1) * 8 + r;
                    int nb   = (wn * WN + j * 16) * 2 + (sub >> 1) * 16;
                    uint32_t so = SWZ(krow * 128 + nb);
                    ldm_x4_t(bh[j], BhB + so);
                    ldm_x4_t(bl[j], BlB + so);
                }
            }
#pragma unroll
            for (int mi = 0; mi < 4; mi++)
#pragma unroll
                for (int j = 0; j < NJ; j++)
#pragma unroll
                    for (int s2 = 0; s2 < 2; s2++) {
                        float* c = acc[mi][j * 2 + s2];
                        mma16816(c, ah[mi], &bh[j][s2 * 2]);
                        mma16816(c, ah[mi], &bl[j][s2 * 2]);
                        mma16816(c, al[mi], &bh[j][s2 * 2]);
                    }
        }
        __syncthreads();
    }

    // ---------------- epilogue (register -> global) ----------------
    int qr = lane >> 2;
    int qc = (lane & 3) * 2;
#pragma unroll
    for (int mi = 0; mi < 4; mi++) {
#pragma unroll
        for (int jj = 0; jj < NJ * 2; jj++) {
            int cg = n0 + wn * WN + (jj >> 1) * 16 + (jj & 1) * 8 + qc;
#pragma unroll
            for (int rr = 0; rr < 2; rr++) {
                int rg = m0 + wm * 64 + mi * 16 + qr + rr * 8;
                float c0 = acc[mi][jj][rr * 2 + 0];
                float c1 = acc[mi][jj][rr * 2 + 1];
                if (bias) { c0 += bias[cg]; c1 += bias[cg + 1]; }
                if (mode == 0) {
                    float* o = (float*)outHi + (size_t)zb * ofsCb + (size_t)zh * ofsCh;
                    *(float2*)&o[(size_t)rg * ldc + cg] = make_float2(c0, c1);
                } else if (mode == 4) {
                    c0 += resid[(size_t)rg * ldr + cg];
                    c1 += resid[(size_t)rg * ldr + cg + 1];
                    float* o = (float*)outHi + (size_t)zb * ofsCb + (size_t)zh * ofsCh;
                    *(float2*)&o[(size_t)rg * ldc + cg] = make_float2(c0, c1);
                } else {
                    if (mode == 3) {
                        c0 = 0.5f * c0 * (1.0f + erff(c0 * 0.70710678118654752f));
                        c1 = 0.5f * c1 * (1.0f + erff(c1 * 0.70710678118654752f));
                    }
                    bf16* ohi = (bf16*)outHi + (size_t)zb * ofsCb + (size_t)zh * ofsCh;
                    bf16* olo = (bf16*)outLo + (size_t)zb * ofsCb + (size_t)zh * ofsCh;
                    bf16 h0, l0, h1, l1;
                    split2(c0, h0, l0); split2(c1, h1, l1);
                    __nv_bfloat162 hv; hv.x = h0; hv.y = h1;
                    __nv_bfloat162 lv; lv.x = l0; lv.y = l1;
                    *(__nv_bfloat162*)&ohi[(size_t)rg * ldc + cg] = hv;
                    *(__nv_bfloat162*)&olo[(size_t)rg * ldc + cg] = lv;
                }
            }
        }
    }
}

// ============================ LayerNorm + split ============================
__global__ void ln_split_kernel(const float* __restrict__ x,
                                const float* __restrict__ gamma,
                                const float* __restrict__ beta,
                                bf16* __restrict__ ohi, bf16* __restrict__ olo) {
    int row = blockIdx.x;
    const float* xr = x + (size_t)row * EMB;
    int tid = threadIdx.x;
    float v[4];
    float s = 0.f, s2 = 0.f;
#pragma unroll
    for (int i = 0; i < 4; i++) {
        float t = xr[tid + i * 256];
        v[i] = t; s += t; s2 += t * t;
    }
#pragma unroll
    for (int o = 16; o > 0; o >>= 1) {
        s  += __shfl_down_sync(0xFFFFFFFFu, s,  o);
        s2 += __shfl_down_sync(0xFFFFFFFFu, s2, o);
    }
    __shared__ float rs[8], rs2[8], mu_s, rstd_s;
    int wid = tid >> 5, lane = tid & 31;
    if (lane == 0) { rs[wid] = s; rs2[wid] = s2; }
    __syncthreads();
    if (wid == 0) {
        float a  = (lane < 8) ? rs[lane]  : 0.f;
        float a2 = (lane < 8) ? rs2[lane] : 0.f;
#pragma unroll
        for (int o = 4; o > 0; o >>= 1) {
            a  += __shfl_down_sync(0xFFFFFFFFu, a,  o);
            a2 += __shfl_down_sync(0xFFFFFFFFu, a2, o);
        }
        if (lane == 0) {
            float mu = a * (1.0f / EMB);
            mu_s = mu;
            rstd_s = rsqrtf(a2 * (1.0f / EMB) - mu * mu + 1e-6f);
        }
    }
    __syncthreads();
    float mu = mu_s, rstd = rstd_s;
#pragma unroll
    for (int i = 0; i < 4; i++) {
        int c = tid + i * 256;
        float val = (v[i] - mu) * rstd * gamma[c] + beta[c];
        bf16 h_, l_; split2(val, h_, l_);
        ohi[(size_t)row * EMB + c] = h_;
        olo[(size_t)row * EMB + c] = l_;
    }
}

// ============================ weight transpose + split ============================
__global__ void tsplit_kernel(const float* __restrict__ W, int K, int N,
                              bf16* __restrict__ Thi, bf16* __restrict__ Tlo) {
    __shared__ float t[32][33];
    int n0 = blockIdx.x * 32, k0 = blockIdx.y * 32;
    int tx = threadIdx.x, ty = threadIdx.y;
#pragma unroll
    for (int i = ty; i < 32; i += 8)
        t[i][tx] = W[(size_t)(k0 + i) * N + n0 + tx];
    __syncthreads();
#pragma unroll
    for (int i = ty; i < 32; i += 8) {
        float v = t[tx][i];
        bf16 h_, l_; split2(v, h_, l_);
        size_t oi = (size_t)(n0 + i) * K + k0 + tx;
        Thi[oi] = h_; Tlo[oi] = l_;
    }
}

// ============================ softmax + split ============================
__global__ void softmax_split_kernel(const float* __restrict__ S,
                                     bf16* __restrict__ Phi, bf16* __restrict__ Plo) {
    const float* p = S + (size_t)blockIdx.x * SEQ;
    bf16* phi = Phi + (size_t)blockIdx.x * SEQ;
    bf16* plo = Plo + (size_t)blockIdx.x * SEQ;
    int tid = threadIdx.x;
    float v[8];
    float m = -1e30f;
#pragma unroll
    for (int i = 0; i < 8; i++) {
        v[i] = p[tid + i * 256];
        m = fmaxf(m, v[i]);
    }
#pragma unroll
    for (int o = 16; o > 0; o >>= 1)
        m = fmaxf(m, __shfl_down_sync(0xFFFFFFFFu, m, o));
    __shared__ float rm[8], m_s, s_s;
    int wid = tid >> 5, lane = tid & 31;
    if (lane == 0) rm[wid] = m;
    __syncthreads();
    if (wid == 0) {
        float a = (lane < 8) ? rm[lane] : -1e30f;
#pragma unroll
        for (int o = 4; o > 0; o >>= 1)
            a = fmaxf(a, __shfl_down_sync(0xFFFFFFFFu, a, o));
        if (lane == 0) m_s = a;
    }
    __syncthreads();
    m = m_s;
    float s = 0.f;
#pragma unroll
    for (int i = 0; i < 8; i++) { v[i] = __expf(v[i] - m); s += v[i]; }
#pragma unroll
    for (int o = 16; o > 0; o >>= 1)
        s += __shfl_down_sync(0xFFFFFFFFu, s, o);
    if (lane == 0) rm[wid] = s;
    __syncthreads();
    if (wid == 0) {
        float a = (lane < 8) ? rm[lane] : 0.f;
#pragma unroll
        for (int o = 4; o > 0; o >>= 1)
            a += __shfl_down_sync(0xFFFFFFFFu, a, o);
        if (lane == 0) s_s = a;
    }
    __syncthreads();
    float inv = 1.0f / s_s;
#pragma unroll
    for (int i = 0; i < 8; i++) {
        float val = v[i] * inv;
        bf16 h_, l_; split2(val, h_, l_);
        phi[tid + i * 256] = h_;
        plo[tid + i * 256] = l_;
    }
}

// ============================ launch ============================
extern "C" void kernel_launch(void* const* d_in, const int* in_sizes, int n_in,
                              void* d_out, int out_size) {
    const float* x   = (const float*)d_in[0];
    const float* Wq  = (const float*)d_in[1];
    const float* bq  = (const float*)d_in[2];
    const float* Wk  = (const float*)d_in[3];
    const float* bk  = (const float*)d_in[4];
    const float* Wv  = (const float*)d_in[5];
    const float* bv  = (const float*)d_in[6];
    const float* g1  = (const float*)d_in[7];
    const float* be1 = (const float*)d_in[8];
    const float* g2  = (const float*)d_in[9];
    const float* be2 = (const float*)d_in[10];
    const float* W1  = (const float*)d_in[11];
    const float* b1  = (const float*)d_in[12];
    const float* W2  = (const float*)d_in[13];
    const float* b2  = (const float*)d_in[14];
    float* out = (float*)d_out;

    bf16 *hhi, *hlo, *wqhi, *wqlo, *wkhi, *wklo, *wvhi, *wvlo;
    bf16 *w1hi, *w1lo, *w2hi, *w2lo, *qhi, *qlo, *khi, *klo, *vhi, *vlo;
    bf16 *Phi, *Plo, *h2hi, *h2lo, *ffhi, *fflo;
    float *S, *attn;
    cudaGetSymbolAddress((void**)&hhi,  g_hhi);  cudaGetSymbolAddress((void**)&hlo,  g_hlo);
    cudaGetSymbolAddress((void**)&wqhi, g_wqhi); cudaGetSymbolAddress((void**)&wqlo, g_wqlo);
    cudaGetSymbolAddress((void**)&wkhi, g_wkhi); cudaGetSymbolAddress((void**)&wklo, g_wklo);
    cudaGetSymbolAddress((void**)&wvhi, g_wvhi); cudaGetSymbolAddress((void**)&wvlo, g_wvlo);
    cudaGetSymbolAddress((void**)&w1hi, g_w1hi); cudaGetSymbolAddress((void**)&w1lo, g_w1lo);
    cudaGetSymbolAddress((void**)&w2hi, g_w2hi); cudaGetSymbolAddress((void**)&w2lo, g_w2lo);
    cudaGetSymbolAddress((void**)&qhi,  g_qhi);  cudaGetSymbolAddress((void**)&qlo,  g_qlo);
    cudaGetSymbolAddress((void**)&khi,  g_khi);  cudaGetSymbolAddress((void**)&klo,  g_klo);
    cudaGetSymbolAddress((void**)&vhi,  g_vhi);  cudaGetSymbolAddress((void**)&vlo,  g_vlo);
    cudaGetSymbolAddress((void**)&S,    g_S);
    cudaGetSymbolAddress((void**)&Phi,  g_Phi);  cudaGetSymbolAddress((void**)&Plo,  g_Plo);
    cudaGetSymbolAddress((void**)&attn, g_attn);
    cudaGetSymbolAddress((void**)&h2hi, g_h2hi); cudaGetSymbolAddress((void**)&h2lo, g_h2lo);
    cudaGetSymbolAddress((void**)&ffhi, g_ffhi); cudaGetSymbolAddress((void**)&fflo, g_fflo);

    const int SMEM_NT = 2 * (2 * 16384 + 2 * 16384);   // 131072  (TN=128)
    const int SMEM_T  = 2 * (2 * 16384 + 2 * 8192);    //  98304  (TN=64 trans)
    cudaFuncSetAttribute(gemmw_kernel<128, false>, cudaFuncAttributeMaxDynamicSharedMemorySize, SMEM_NT);
    cudaFuncSetAttribute(gemmw_kernel<64, true>,   cudaFuncAttributeMaxDynamicSharedMemorySize, SMEM_T);

    dim3 tb(32, 8);
    tsplit_kernel<<<dim3(EMB / 32, EMB / 32), tb>>>(Wq, EMB, EMB, wqhi, wqlo);
    tsplit_kernel<<<dim3(EMB / 32, EMB / 32), tb>>>(Wk, EMB, EMB, wkhi, wklo);
    tsplit_kernel<<<dim3(EMB / 32, EMB / 32), tb>>>(Wv, EMB, EMB, wvhi, wvlo);
    tsplit_kernel<<<dim3(DFF / 32, EMB / 32), tb>>>(W1, EMB, DFF, w1hi, w1lo);
    tsplit_kernel<<<dim3(EMB / 32, DFF / 32), tb>>>(W2, DFF, EMB, w2hi, w2lo);

    ln_split_kernel<<<TOK, 256>>>(x, g1, be1, hhi, hlo);

    // QKV projections: [4096,1024] x [1024,1024]^T
    {
        dim3 grid(EMB / 128, TOK / 128, 1);
        gemmw_kernel<128, false><<<grid, 256, SMEM_NT>>>(
            hhi, hlo, EMB, 0, 0, wqhi, wqlo, EMB, 0, 0,
            bq, nullptr, 0, 0, 0, qhi, qlo, EMB, 0, 0, EMB, 1);
        gemmw_kernel<128, false><<<grid, 256, SMEM_NT>>>(
            hhi, hlo, EMB, 0, 0, wkhi, wklo, EMB, 0, 0,
            bk, nullptr, 0, 0, 0, khi, klo, EMB, 0, 0, EMB, 1);
        gemmw_kernel<128, false><<<grid, 256, SMEM_NT>>>(
            hhi, hlo, EMB, 0, 0, wvhi, wvlo, EMB, 0, 0,
            bv, nullptr, 0, 0, 0, vhi, vlo, EMB, 0, 0, EMB, 1);
    }

    // scores: per (b,h)  S[2048,2048] = q @ k^T, K=64
    {
        dim3 grid(SEQ / 128, SEQ / 128, BATCH * HEADS);
        gemmw_kernel<128, false><<<grid, 256, SMEM_NT>>>(
            qhi, qlo, EMB, (long)SEQ * EMB, DH,
            khi, klo, EMB, (long)SEQ * EMB, DH,
            nullptr, nullptr, 0, 0, 0,
            S, nullptr, SEQ, (long)HEADS * SEQ * SEQ, (long)SEQ * SEQ,
            DH, 0);
    }

    softmax_split_kernel<<<BATCH * HEADS * SEQ, 256>>>(S, Phi, Plo);

    // PV: per (b,h)  attn[2048,64] = P @ v, K=2048; + residual x
    {
        dim3 grid(1, SEQ / 128, BATCH * HEADS);
        gemmw_kernel<64, true><<<grid, 256, SMEM_T>>>(
            Phi, Plo, SEQ, (long)HEADS * SEQ * SEQ, (long)SEQ * SEQ,
            vhi, vlo, EMB, (long)SEQ * EMB, DH,
            nullptr,
            x, EMB, (long)SEQ * EMB, DH,
            attn, nullptr, EMB, (long)SEQ * EMB, DH,
            SEQ, 4);
    }

    ln_split_kernel<<<TOK, 256>>>(attn, g2, be2, h2hi, h2lo);

    // FFN1: [4096,4096] = h2 @ W1^T + b1, gelu -> split
    {
        dim3 grid(DFF / 128, TOK / 128, 1);
        gemmw_kernel<128, false><<<grid, 256, SMEM_NT>>>(
            h2hi, h2lo, EMB, 0, 0, w1hi, w1lo, EMB, 0, 0,
            b1, nullptr, 0, 0, 0, ffhi, fflo, DFF, 0, 0, EMB, 3);
    }

    // FFN2: out = ff @ W2^T + b2 + attn
    {
        dim3 grid(EMB / 128, TOK / 128, 1);
        gemmw_kernel<128, false><<<grid, 256, SMEM_NT>>>(
            ffhi, fflo, DFF, 0, 0, w2hi, w2lo, DFF, 0, 0,
            b2, attn, EMB, 0, 0, out, nullptr, EMB, 0, 0, DFF, 4);
    }
}

// round 5
// speedup vs baseline: 3.6737x; 1.1967x over previous
#include <cuda_runtime.h>
#include <cuda_bf16.h>
#include <math.h>
#include <stdint.h>

#define EMB   1024
#define DFF   4096
#define HEADS 16
#define DH    64
#define BATCH 2
#define SEQ   2048
#define TOK   (BATCH*SEQ)

typedef __nv_bfloat16 bf16;

// ============================ scratch (static, no allocs) ============================
__device__ __align__(1024) bf16 g_hhi [(size_t)TOK*EMB];
__device__ __align__(1024) bf16 g_hlo [(size_t)TOK*EMB];
__device__ __align__(1024) bf16 g_wqhi[(size_t)EMB*EMB];
__device__ __align__(1024) bf16 g_wqlo[(size_t)EMB*EMB];
__device__ __align__(1024) bf16 g_wkhi[(size_t)EMB*EMB];
__device__ __align__(1024) bf16 g_wklo[(size_t)EMB*EMB];
__device__ __align__(1024) bf16 g_wvhi[(size_t)EMB*EMB];
__device__ __align__(1024) bf16 g_wvlo[(size_t)EMB*EMB];
__device__ __align__(1024) bf16 g_w1hi[(size_t)DFF*EMB];
__device__ __align__(1024) bf16 g_w1lo[(size_t)DFF*EMB];
__device__ __align__(1024) bf16 g_w2hi[(size_t)EMB*DFF];
__device__ __align__(1024) bf16 g_w2lo[(size_t)EMB*DFF];
__device__ __align__(1024) bf16 g_qhi [(size_t)TOK*EMB];
__device__ __align__(1024) bf16 g_qlo [(size_t)TOK*EMB];
__device__ __align__(1024) bf16 g_khi [(size_t)TOK*EMB];
__device__ __align__(1024) bf16 g_klo [(size_t)TOK*EMB];
__device__ __align__(1024) bf16 g_vhi [(size_t)TOK*EMB];
__device__ __align__(1024) bf16 g_vlo [(size_t)TOK*EMB];
__device__ __align__(1024) float g_attn[(size_t)TOK*EMB];
__device__ __align__(1024) bf16 g_h2hi[(size_t)TOK*EMB];
__device__ __align__(1024) bf16 g_h2lo[(size_t)TOK*EMB];
__device__ __align__(1024) bf16 g_ffhi[(size_t)TOK*DFF];
__device__ __align__(1024) bf16 g_fflo[(size_t)TOK*DFF];

// ============================ PTX helpers ============================
__device__ __forceinline__ uint32_t smem_u32(const void* p) {
    uint32_t a;
    asm("{ .reg .u64 t; cvta.to.shared.u64 t, %1; cvt.u32.u64 %0, t; }" : "=r"(a) : "l"(p));
    return a;
}
__device__ __forceinline__ void cpasync16(uint32_t dst, const void* src) {
    asm volatile("cp.async.cg.shared.global [%0], [%1], 16;\n" :: "r"(dst), "l"(src));
}
#define CP_COMMIT()  asm volatile("cp.async.commit_group;\n" ::: "memory")
#define CP_WAIT0()   asm volatile("cp.async.wait_group 0;\n" ::: "memory")
#define CP_WAIT1()   asm volatile("cp.async.wait_group 1;\n" ::: "memory")

__device__ __forceinline__ void ldm_x4(uint32_t* r, uint32_t addr) {
    asm volatile("ldmatrix.sync.aligned.m8n8.x4.shared.b16 {%0,%1,%2,%3}, [%4];"
                 : "=r"(r[0]), "=r"(r[1]), "=r"(r[2]), "=r"(r[3]) : "r"(addr));
}
__device__ __forceinline__ void ldm_x4_t(uint32_t* r, uint32_t addr) {
    asm volatile("ldmatrix.sync.aligned.m8n8.x4.trans.shared.b16 {%0,%1,%2,%3}, [%4];"
                 : "=r"(r[0]), "=r"(r[1]), "=r"(r[2]), "=r"(r[3]) : "r"(addr));
}
__device__ __forceinline__ void mma16816(float* d, const uint32_t* a, const uint32_t* b) {
    asm volatile(
        "mma.sync.aligned.m16n8k16.row.col.f32.bf16.bf16.f32 "
        "{%0,%1,%2,%3}, {%4,%5,%6,%7}, {%8,%9}, {%0,%1,%2,%3};"
        : "+f"(d[0]), "+f"(d[1]), "+f"(d[2]), "+f"(d[3])
        : "r"(a[0]), "r"(a[1]), "r"(a[2]), "r"(a[3]), "r"(b[0]), "r"(b[1]));
}

#define SWZ(o) ((o) ^ (((o) >> 3) & 0x70))

__device__ __forceinline__ void split2(float v, bf16& hi, bf16& lo) {
    hi = __float2bfloat16(v);
    lo = __float2bfloat16(v - __bfloat162float(hi));
}
__device__ __forceinline__ void splitpack(float p0, float p1, uint32_t& hiw, uint32_t& low) {
    bf16 h0 = __float2bfloat16(p0), h1 = __float2bfloat16(p1);
    float l0 = p0 - __bfloat162float(h0);
    float l1 = p1 - __bfloat162float(h1);
    __nv_bfloat162 hv; hv.x = h0; hv.y = h1;
    __nv_bfloat162 lv; lv.x = __float2bfloat16(l0); lv.y = __float2bfloat16(l1);
    hiw = *(uint32_t*)&hv; low = *(uint32_t*)&lv;
}

// ============================ split-precision mma.sync GEMM ============================
// C[M,N] = (Ahi+Alo)[M,K] @ (Bhi+Blo)[N,K]^T, CTA tile 128 x 128, KC=64.
// modes: 0 fp32(+bias); 1 split bf16(+bias); 3 bias+gelu->split; 4 (+bias)+resid->fp32
__global__ void __launch_bounds__(256)
gemmw_kernel(const bf16* __restrict__ Ahi, const bf16* __restrict__ Alo, int lda,
             const bf16* __restrict__ Bhi, const bf16* __restrict__ Blo, int ldb,
             const float* __restrict__ bias,
             const float* __restrict__ resid, int ldr,
             void* outHi, void* outLo, int ldc,
             int K, int mode) {
    constexpr int TN = 128;
    constexpr int ABYTES = 128 * 128;
    constexpr int BBYTES = TN * 128;
    constexpr int STAGE  = 2 * ABYTES + 2 * BBYTES;
    constexpr int WN = TN / 4;
    constexpr int NJ = WN / 16;

    extern __shared__ char smem[];
    uint32_t sb = smem_u32(smem);

    int tid = threadIdx.x;
    int wid = tid >> 5, lane = tid & 31;
    int wm = wid >> 2, wn = wid & 3;
    int sub = lane >> 3, r = lane & 7;

    int m0 = blockIdx.y * 128;
    int n0 = blockIdx.x * TN;

    float acc[4][NJ * 2][4];
#pragma unroll
    for (int i = 0; i < 4; i++)
#pragma unroll
        for (int j = 0; j < NJ * 2; j++)
#pragma unroll
            for (int t = 0; t < 4; t++) acc[i][j][t] = 0.f;

    const int nIter = K / 64;

    auto load_stage = [&](int it, int s) {
        int k0 = it * 64;
        uint32_t AhB = sb + s * STAGE;
        uint32_t AlB = AhB + ABYTES;
        uint32_t BhB = AlB + ABYTES;
        uint32_t BlB = BhB + BBYTES;
#pragma unroll
        for (int t = 0; t < 4; t++) {
            int idx = tid + t * 256;
            int row = idx >> 3, seg = idx & 7;
            size_t go = (size_t)(m0 + row) * lda + k0 + seg * 8;
            uint32_t so = SWZ(row * 128 + seg * 16);
            cpasync16(AhB + so, Ahi + go);
            cpasync16(AlB + so, Alo + go);
        }
#pragma unroll
        for (int t = 0; t < 4; t++) {
            int idx = tid + t * 256;
            int row = idx >> 3, seg = idx & 7;
            size_t go = (size_t)(n0 + row) * ldb + k0 + seg * 8;
            uint32_t so = SWZ(row * 128 + seg * 16);
            cpasync16(BhB + so, Bhi + go);
            cpasync16(BlB + so, Blo + go);
        }
        CP_COMMIT();
    };

    load_stage(0, 0);

    for (int it = 0; it < nIter; it++) {
        int s = it & 1;
        if (it + 1 < nIter) { load_stage(it + 1, s ^ 1); CP_WAIT1(); }
        else CP_WAIT0();
        __syncthreads();

        uint32_t AhB = sb + s * STAGE;
        uint32_t AlB = AhB + ABYTES;
        uint32_t BhB = AlB + ABYTES;
        uint32_t BlB = BhB + BBYTES;

#pragma unroll
        for (int ks = 0; ks < 4; ks++) {
            uint32_t ah[4][4], al[4][4];
#pragma unroll
            for (int mi = 0; mi < 4; mi++) {
                int row = wm * 64 + mi * 16 + (sub & 1) * 8 + r;
                int kb  = ks * 32 + (sub >> 1) * 16;
                uint32_t so = SWZ(row * 128 + kb);
                ldm_x4(ah[mi], AhB + so);
                ldm_x4(al[mi], AlB + so);
            }
            uint32_t bh[NJ][4], bl[NJ][4];
#pragma unroll
            for (int j = 0; j < NJ; j++) {
                int nrow = wn * WN + j * 16 + (sub >> 1) * 8 + r;
                int kb   = ks * 32 + (sub & 1) * 16;
                uint32_t so = SWZ(nrow * 128 + kb);
                ldm_x4(bh[j], BhB + so);
                ldm_x4(bl[j], BlB + so);
            }
#pragma unroll
            for (int mi = 0; mi < 4; mi++)
#pragma unroll
                for (int j = 0; j < NJ; j++)
#pragma unroll
                    for (int s2 = 0; s2 < 2; s2++) {
                        float* c = acc[mi][j * 2 + s2];
                        mma16816(c, ah[mi], &bh[j][s2 * 2]);
                        mma16816(c, ah[mi], &bl[j][s2 * 2]);
                        mma16816(c, al[mi], &bh[j][s2 * 2]);
                    }
        }
        __syncthreads();
    }

    int qr = lane >> 2;
    int qc = (lane & 3) * 2;
#pragma unroll
    for (int mi = 0; mi < 4; mi++) {
#pragma unroll
        for (int jj = 0; jj < NJ * 2; jj++) {
            int cg = n0 + wn * WN + (jj >> 1) * 16 + (jj & 1) * 8 + qc;
#pragma unroll
            for (int rr = 0; rr < 2; rr++) {
                int rg = m0 + wm * 64 + mi * 16 + qr + rr * 8;
                float c0 = acc[mi][jj][rr * 2 + 0];
                float c1 = acc[mi][jj][rr * 2 + 1];
                if (bias) { c0 += bias[cg]; c1 += bias[cg + 1]; }
                if (mode == 0) {
                    float* o = (float*)outHi;
                    *(float2*)&o[(size_t)rg * ldc + cg] = make_float2(c0, c1);
                } else if (mode == 4) {
                    c0 += resid[(size_t)rg * ldr + cg];
                    c1 += resid[(size_t)rg * ldr + cg + 1];
                    float* o = (float*)outHi;
                    *(float2*)&o[(size_t)rg * ldc + cg] = make_float2(c0, c1);
                } else {
                    if (mode == 3) {
                        c0 = 0.5f * c0 * (1.0f + erff(c0 * 0.70710678118654752f));
                        c1 = 0.5f * c1 * (1.0f + erff(c1 * 0.70710678118654752f));
                    }
                    bf16* ohi = (bf16*)outHi;
                    bf16* olo = (bf16*)outLo;
                    bf16 h0, l0, h1, l1;
                    split2(c0, h0, l0); split2(c1, h1, l1);
                    __nv_bfloat162 hv; hv.x = h0; hv.y = h1;
                    __nv_bfloat162 lv; lv.x = l0; lv.y = l1;
                    *(__nv_bfloat162*)&ohi[(size_t)rg * ldc + cg] = hv;
                    *(__nv_bfloat162*)&olo[(size_t)rg * ldc + cg] = lv;
                }
            }
        }
    }
}

// ============================ fused flash attention ============================
// Per CTA: (b,h) = blockIdx.y, q-tile of 128 rows = blockIdx.x.
// Online softmax, split-precision QK^T and PV, fused +x residual -> attn fp32.
__global__ void __launch_bounds__(256)
fattn_kernel(const bf16* __restrict__ qhi, const bf16* __restrict__ qlo,
             const bf16* __restrict__ khi, const bf16* __restrict__ klo,
             const bf16* __restrict__ vhi, const bf16* __restrict__ vlo,
             const float* __restrict__ x, float* __restrict__ attn) {
    constexpr int BUF = 128 * 128;   // 128 rows x 128B (64 bf16)
    extern __shared__ char smem[];
    uint32_t sb = smem_u32(smem);
    const uint32_t QHb = sb, QLb = sb + BUF;
    const uint32_t ST0 = sb + 2 * BUF;   // + s*4*BUF : KH,KL,VH,VL

    int tid = threadIdx.x, wid = tid >> 5, lane = tid & 31;
    int sub = lane >> 3, r = lane & 7;
    int z = blockIdx.y, zb = z >> 4, zh = z & 15;
    int m0 = blockIdx.x * 128;

    const size_t rowbase = (size_t)zb * SEQ;
    const int colofs = zh * DH;

    // Q tile load: 128 rows x 128B = 1024 16B chunks per buffer
#pragma unroll
    for (int t = 0; t < 4; t++) {
        int idx = tid + t * 256;
        int row = idx >> 3, seg = idx & 7;
        size_t go = (rowbase + m0 + row) * EMB + colofs + seg * 8;
        uint32_t so = SWZ(row * 128 + seg * 16);
        cpasync16(QHb + so, qhi + go);
        cpasync16(QLb + so, qlo + go);
    }
    CP_COMMIT();

    auto load_kv = [&](int j, int s) {
        uint32_t base = ST0 + s * 4 * BUF;
        int k0 = j * 128;
#pragma unroll
        for (int t = 0; t < 4; t++) {
            int idx = tid + t * 256;
            int row = idx >> 3, seg = idx & 7;
            size_t go = (rowbase + k0 + row) * EMB + colofs + seg * 8;
            uint32_t so = SWZ(row * 128 + seg * 16);
            cpasync16(base + 0 * BUF + so, khi + go);
            cpasync16(base + 1 * BUF + so, klo + go);
            cpasync16(base + 2 * BUF + so, vhi + go);
            cpasync16(base + 3 * BUF + so, vlo + go);
        }
        CP_COMMIT();
    };

    load_kv(0, 0);
    CP_WAIT1();            // Q complete
    __syncthreads();

    // Q fragments held in registers for all 16 kv tiles
    uint32_t qh[4][4], ql[4][4];
#pragma unroll
    for (int ks = 0; ks < 4; ks++) {
        int row = wid * 16 + (sub & 1) * 8 + r;
        int kb  = ks * 32 + (sub >> 1) * 16;
        uint32_t so = SWZ(row * 128 + kb);
        ldm_x4(qh[ks], QHb + so);
        ldm_x4(ql[ks], QLb + so);
    }

    float mr0 = -1e30f, mr1 = -1e30f, lr0 = 0.f, lr1 = 0.f;
    float oacc[8][4];
#pragma unroll
    for (int d = 0; d < 8; d++)
#pragma unroll
        for (int t = 0; t < 4; t++) oacc[d][t] = 0.f;

    for (int j = 0; j < SEQ / 128; j++) {
        int s = j & 1;
        if (j + 1 < SEQ / 128) { load_kv(j + 1, s ^ 1); CP_WAIT1(); }
        else CP_WAIT0();
        __syncthreads();

        uint32_t KHb = ST0 + s * 4 * BUF;
        uint32_t KLb = KHb + BUF, VHb = KLb + BUF, VLb = VHb + BUF;

        // ---- S = Q K^T (16 q x 128 kv per warp), split 3-MMA ----
        float sacc[16][4];
#pragma unroll
        for (int g = 0; g < 16; g++)
#pragma unroll
            for (int t = 0; t < 4; t++) sacc[g][t] = 0.f;

#pragma unroll
        for (int ks = 0; ks < 4; ks++) {
#pragma unroll
            for (int g = 0; g < 8; g++) {
                uint32_t bh[4], bl[4];
                int nrow = g * 16 + (sub >> 1) * 8 + r;
                int kb   = ks * 32 + (sub & 1) * 16;
                uint32_t so = SWZ(nrow * 128 + kb);
                ldm_x4(bh, KHb + so);
                ldm_x4(bl, KLb + so);
#pragma unroll
                for (int s2 = 0; s2 < 2; s2++) {
                    float* c = sacc[g * 2 + s2];
                    mma16816(c, qh[ks], &bh[s2 * 2]);
                    mma16816(c, qh[ks], &bl[s2 * 2]);
                    mma16816(c, ql[ks], &bh[s2 * 2]);
                }
            }
        }

        // ---- online softmax (rows r0 = lane>>2, r1 = r0+8) ----
        float mx0 = -1e30f, mx1 = -1e30f;
#pragma unroll
        for (int g = 0; g < 16; g++) {
            mx0 = fmaxf(mx0, fmaxf(sacc[g][0], sacc[g][1]));
            mx1 = fmaxf(mx1, fmaxf(sacc[g][2], sacc[g][3]));
        }
        mx0 = fmaxf(mx0, __shfl_xor_sync(0xFFFFFFFFu, mx0, 1));
        mx0 = fmaxf(mx0, __shfl_xor_sync(0xFFFFFFFFu, mx0, 2));
        mx1 = fmaxf(mx1, __shfl_xor_sync(0xFFFFFFFFu, mx1, 1));
        mx1 = fmaxf(mx1, __shfl_xor_sync(0xFFFFFFFFu, mx1, 2));

        float mn0 = fmaxf(mr0, mx0), mn1 = fmaxf(mr1, mx1);
        float a0 = __expf(mr0 - mn0), a1 = __expf(mr1 - mn1);
        mr0 = mn0; mr1 = mn1;

        float sum0 = 0.f, sum1 = 0.f;
#pragma unroll
        for (int g = 0; g < 16; g++) {
            sacc[g][0] = __expf(sacc[g][0] - mn0);
            sacc[g][1] = __expf(sacc[g][1] - mn0);
            sacc[g][2] = __expf(sacc[g][2] - mn1);
            sacc[g][3] = __expf(sacc[g][3] - mn1);
            sum0 += sacc[g][0] + sacc[g][1];
            sum1 += sacc[g][2] + sacc[g][3];
        }
        sum0 += __shfl_xor_sync(0xFFFFFFFFu, sum0, 1);
        sum0 += __shfl_xor_sync(0xFFFFFFFFu, sum0, 2);
        sum1 += __shfl_xor_sync(0xFFFFFFFFu, sum1, 1);
        sum1 += __shfl_xor_sync(0xFFFFFFFFu, sum1, 2);
        lr0 = lr0 * a0 + sum0;
        lr1 = lr1 * a1 + sum1;
#pragma unroll
        for (int d = 0; d < 8; d++) {
            oacc[d][0] *= a0; oacc[d][1] *= a0;
            oacc[d][2] *= a1; oacc[d][3] *= a1;
        }

        // ---- O += P V (P in registers -> A frags, V via ldmatrix.trans) ----
#pragma unroll
        for (int t = 0; t < 8; t++) {
            uint32_t pah[4], pal[4];
            splitpack(sacc[2 * t][0],     sacc[2 * t][1],     pah[0], pal[0]);
            splitpack(sacc[2 * t][2],     sacc[2 * t][3],     pah[1], pal[1]);
            splitpack(sacc[2 * t + 1][0], sacc[2 * t + 1][1], pah[2], pal[2]);
            splitpack(sacc[2 * t + 1][2], sacc[2 * t + 1][3], pah[3], pal[3]);
#pragma unroll
            for (int gd = 0; gd < 4; gd++) {
                uint32_t vh4[4], vl4[4];
                int krow = t * 16 + (sub & 1) * 8 + r;
                int nb   = gd * 32 + (sub >> 1) * 16;
                uint32_t so = SWZ(krow * 128 + nb);
                ldm_x4_t(vh4, VHb + so);
                ldm_x4_t(vl4, VLb + so);
#pragma unroll
                for (int s2 = 0; s2 < 2; s2++) {
                    float* o = oacc[gd * 2 + s2];
                    mma16816(o, pah, &vh4[s2 * 2]);
                    mma16816(o, pah, &vl4[s2 * 2]);
                    mma16816(o, pal, &vh4[s2 * 2]);
                }
            }
        }
        __syncthreads();   // compute done before next stage overwrite
    }

    // ---- epilogue: O/l + x -> attn (fp32) ----
    float li0 = 1.f / lr0, li1 = 1.f / lr1;
    int qr = lane >> 2, qc = (lane & 3) * 2;
    size_t row0 = rowbase + m0 + wid * 16 + qr;
    size_t row1 = row0 + 8;
#pragma unroll
    for (int gd = 0; gd < 8; gd++) {
        int cg = colofs + gd * 8 + qc;
        float2 xr0 = *(const float2*)&x[row0 * EMB + cg];
        float2 xr1 = *(const float2*)&x[row1 * EMB + cg];
        float2 o0 = make_float2(oacc[gd][0] * li0 + xr0.x, oacc[gd][1] * li0 + xr0.y);
        float2 o1 = make_float2(oacc[gd][2] * li1 + xr1.x, oacc[gd][3] * li1 + xr1.y);
        *(float2*)&attn[row0 * EMB + cg] = o0;
        *(float2*)&attn[row1 * EMB + cg] = o1;
    }
}

// ============================ LayerNorm + split ============================
__global__ void ln_split_kernel(const float* __restrict__ x,
                                const float* __restrict__ gamma,
                                const float* __restrict__ beta,
                                bf16* __restrict__ ohi, bf16* __restrict__ olo) {
    int row = blockIdx.x;
    const float* xr = x + (size_t)row * EMB;
    int tid = threadIdx.x;
    float v[4];
    float s = 0.f, s2 = 0.f;
#pragma unroll
    for (int i = 0; i < 4; i++) {
        float t = xr[tid + i * 256];
        v[i] = t; s += t; s2 += t * t;
    }
#pragma unroll
    for (int o = 16; o > 0; o >>= 1) {
        s  += __shfl_down_sync(0xFFFFFFFFu, s,  o);
        s2 += __shfl_down_sync(0xFFFFFFFFu, s2, o);
    }
    __shared__ float rs[8], rs2[8], mu_s, rstd_s;
    int wid = tid >> 5, lane = tid & 31;
    if (lane == 0) { rs[wid] = s; rs2[wid] = s2; }
    __syncthreads();
    if (wid == 0) {
        float a  = (lane < 8) ? rs[lane]  : 0.f;
        float a2 = (lane < 8) ? rs2[lane] : 0.f;
#pragma unroll
        for (int o = 4; o > 0; o >>= 1) {
            a  += __shfl_down_sync(0xFFFFFFFFu, a,  o);
            a2 += __shfl_down_sync(0xFFFFFFFFu, a2, o);
        }
        if (lane == 0) {
            float mu = a * (1.0f / EMB);
            mu_s = mu;
            rstd_s = rsqrtf(a2 * (1.0f / EMB) - mu * mu + 1e-6f);
        }
    }
    __syncthreads();
    float mu = mu_s, rstd = rstd_s;
#pragma unroll
    for (int i = 0; i < 4; i++) {
        int c = tid + i * 256;
        float val = (v[i] - mu) * rstd * gamma[c] + beta[c];
        bf16 h_, l_; split2(val, h_, l_);
        ohi[(size_t)row * EMB + c] = h_;
        olo[(size_t)row * EMB + c] = l_;
    }
}

// ============================ weight transpose + split ============================
__global__ void tsplit_kernel(const float* __restrict__ W, int K, int N,
                              bf16* __restrict__ Thi, bf16* __restrict__ Tlo) {
    __shared__ float t[32][33];
    int n0 = blockIdx.x * 32, k0 = blockIdx.y * 32;
    int tx = threadIdx.x, ty = threadIdx.y;
#pragma unroll
    for (int i = ty; i < 32; i += 8)
        t[i][tx] = W[(size_t)(k0 + i) * N + n0 + tx];
    __syncthreads();
#pragma unroll
    for (int i = ty; i < 32; i += 8) {
        float v = t[tx][i];
        bf16 h_, l_; split2(v, h_, l_);
        size_t oi = (size_t)(n0 + i) * K + k0 + tx;
        Thi[oi] = h_; Tlo[oi] = l_;
    }
}

// ============================ launch ============================
extern "C" void kernel_launch(void* const* d_in, const int* in_sizes, int n_in,
                              void* d_out, int out_size) {
    const float* x   = (const float*)d_in[0];
    const float* Wq  = (const float*)d_in[1];
    const float* bq  = (const float*)d_in[2];
    const float* Wk  = (const float*)d_in[3];
    const float* bk  = (const float*)d_in[4];
    const float* Wv  = (const float*)d_in[5];
    const float* bv  = (const float*)d_in[6];
    const float* g1  = (const float*)d_in[7];
    const float* be1 = (const float*)d_in[8];
    const float* g2  = (const float*)d_in[9];
    const float* be2 = (const float*)d_in[10];
    const float* W1  = (const float*)d_in[11];
    const float* b1  = (const float*)d_in[12];
    const float* W2  = (const float*)d_in[13];
    const float* b2  = (const float*)d_in[14];
    float* out = (float*)d_out;

    bf16 *hhi, *hlo, *wqhi, *wqlo, *wkhi, *wklo, *wvhi, *wvlo;
    bf16 *w1hi, *w1lo, *w2hi, *w2lo, *qhi, *qlo, *khi, *klo, *vhi, *vlo;
    bf16 *h2hi, *h2lo, *ffhi, *fflo;
    float *attn;
    cudaGetSymbolAddress((void**)&hhi,  g_hhi);  cudaGetSymbolAddress((void**)&hlo,  g_hlo);
    cudaGetSymbolAddress((void**)&wqhi, g_wqhi); cudaGetSymbolAddress((void**)&wqlo, g_wqlo);
    cudaGetSymbolAddress((void**)&wkhi, g_wkhi); cudaGetSymbolAddress((void**)&wklo, g_wklo);
    cudaGetSymbolAddress((void**)&wvhi, g_wvhi); cudaGetSymbolAddress((void**)&wvlo, g_wvlo);
    cudaGetSymbolAddress((void**)&w1hi, g_w1hi); cudaGetSymbolAddress((void**)&w1lo, g_w1lo);
    cudaGetSymbolAddress((void**)&w2hi, g_w2hi); cudaGetSymbolAddress((void**)&w2lo, g_w2lo);
    cudaGetSymbolAddress((void**)&qhi,  g_qhi);  cudaGetSymbolAddress((void**)&qlo,  g_qlo);
    cudaGetSymbolAddress((void**)&khi,  g_khi);  cudaGetSymbolAddress((void**)&klo,  g_klo);
    cudaGetSymbolAddress((void**)&vhi,  g_vhi);  cudaGetSymbolAddress((void**)&vlo,  g_vlo);
    cudaGetSymbolAddress((void**)&attn, g_attn);
    cudaGetSymbolAddress((void**)&h2hi, g_h2hi); cudaGetSymbolAddress((void**)&h2lo, g_h2lo);
    cudaGetSymbolAddress((void**)&ffhi, g_ffhi); cudaGetSymbolAddress((void**)&fflo, g_fflo);

    const int SMEM_G = 2 * (2 * 16384 + 2 * 16384);   // 131072
    const int SMEM_F = 10 * 16384;                     // 163840
    cudaFuncSetAttribute(gemmw_kernel, cudaFuncAttributeMaxDynamicSharedMemorySize, SMEM_G);
    cudaFuncSetAttribute(fattn_kernel, cudaFuncAttributeMaxDynamicSharedMemorySize, SMEM_F);

    dim3 tb(32, 8);
    tsplit_kernel<<<dim3(EMB / 32, EMB / 32), tb>>>(Wq, EMB, EMB, wqhi, wqlo);
    tsplit_kernel<<<dim3(EMB / 32, EMB / 32), tb>>>(Wk, EMB, EMB, wkhi, wklo);
    tsplit_kernel<<<dim3(EMB / 32, EMB / 32), tb>>>(Wv, EMB, EMB, wvhi, wvlo);
    tsplit_kernel<<<dim3(DFF / 32, EMB / 32), tb>>>(W1, EMB, DFF, w1hi, w1lo);
    tsplit_kernel<<<dim3(EMB / 32, DFF / 32), tb>>>(W2, DFF, EMB, w2hi, w2lo);

    ln_split_kernel<<<TOK, 256>>>(x, g1, be1, hhi, hlo);

    // QKV projections
    {
        dim3 grid(EMB / 128, TOK / 128);
        gemmw_kernel<<<grid, 256, SMEM_G>>>(hhi, hlo, EMB, wqhi, wqlo, EMB,
                                            bq, nullptr, 0, qhi, qlo, EMB, EMB, 1);
        gemmw_kernel<<<grid, 256, SMEM_G>>>(hhi, hlo, EMB, wkhi, wklo, EMB,
                                            bk, nullptr, 0, khi, klo, EMB, EMB, 1);
        gemmw_kernel<<<grid, 256, SMEM_G>>>(hhi, hlo, EMB, wvhi, wvlo, EMB,
                                            bv, nullptr, 0, vhi, vlo, EMB, EMB, 1);
    }

    // fused attention (+ residual x) -> attn
    {
        dim3 grid(SEQ / 128, BATCH * HEADS);
        fattn_kernel<<<grid, 256, SMEM_F>>>(qhi, qlo, khi, klo, vhi, vlo, x, attn);
    }

    ln_split_kernel<<<TOK, 256>>>(attn, g2, be2, h2hi, h2lo);

    // FFN1 (+bias, gelu) -> split
    {
        dim3 grid(DFF / 128, TOK / 128);
        gemmw_kernel<<<grid, 256, SMEM_G>>>(h2hi, h2lo, EMB, w1hi, w1lo, EMB,
                                            b1, nullptr, 0, ffhi, fflo, DFF, EMB, 3);
    }

    // FFN2 (+bias, +attn residual) -> d_out
    {
        dim3 grid(EMB / 128, TOK / 128);
        gemmw_kernel<<<grid, 256, SMEM_G>>>(ffhi, fflo, DFF, w2hi, w2lo, DFF,
                                            b2, attn, EMB, out, nullptr, EMB, DFF, 4);
    }
}

// round 6
// speedup vs baseline: 3.7011x; 1.0075x over previous
#include <cuda_runtime.h>
#include <cuda_bf16.h>
#include <math.h>
#include <stdint.h>

#define EMB   1024
#define DFF   4096
#define HEADS 16
#define DH    64
#define BATCH 2
#define SEQ   2048
#define TOK   (BATCH*SEQ)

typedef __nv_bfloat16 bf16;

// ============================ scratch (static, no allocs) ============================
__device__ __align__(1024) bf16 g_hhi  [(size_t)TOK*EMB];
__device__ __align__(1024) bf16 g_hlo  [(size_t)TOK*EMB];
__device__ __align__(1024) bf16 g_wqkvhi[(size_t)3*EMB*EMB];   // [3072,1024] K-major
__device__ __align__(1024) bf16 g_wqkvlo[(size_t)3*EMB*EMB];
__device__ __align__(1024) bf16 g_w1hi [(size_t)DFF*EMB];      // [4096,1024]
__device__ __align__(1024) bf16 g_w1lo [(size_t)DFF*EMB];
__device__ __align__(1024) bf16 g_w2hi [(size_t)EMB*DFF];      // [1024,4096]
__device__ __align__(1024) bf16 g_w2lo [(size_t)EMB*DFF];
__device__ __align__(1024) float g_bqkv[3*EMB];
__device__ __align__(1024) bf16 g_qkvhi[(size_t)TOK*3*EMB];    // [tok,3072]: q|k|v
__device__ __align__(1024) bf16 g_qkvlo[(size_t)TOK*3*EMB];
__device__ __align__(1024) float g_attn[(size_t)TOK*EMB];
__device__ __align__(1024) bf16 g_h2hi [(size_t)TOK*EMB];
__device__ __align__(1024) bf16 g_h2lo [(size_t)TOK*EMB];
__device__ __align__(1024) bf16 g_ffhi [(size_t)TOK*DFF];
__device__ __align__(1024) bf16 g_fflo [(size_t)TOK*DFF];

// ============================ PTX helpers ============================
__device__ __forceinline__ uint32_t smem_u32(const void* p) {
    uint32_t a;
    asm("{ .reg .u64 t; cvta.to.shared.u64 t, %1; cvt.u32.u64 %0, t; }" : "=r"(a) : "l"(p));
    return a;
}
__device__ __forceinline__ void cpasync16(uint32_t dst, const void* src) {
    asm volatile("cp.async.cg.shared.global [%0], [%1], 16;\n" :: "r"(dst), "l"(src));
}
#define CP_COMMIT()  asm volatile("cp.async.commit_group;\n" ::: "memory")
#define CP_WAIT0()   asm volatile("cp.async.wait_group 0;\n" ::: "memory")

__device__ __forceinline__ void ldm_x4(uint32_t* r, uint32_t addr) {
    asm volatile("ldmatrix.sync.aligned.m8n8.x4.shared.b16 {%0,%1,%2,%3}, [%4];"
                 : "=r"(r[0]), "=r"(r[1]), "=r"(r[2]), "=r"(r[3]) : "r"(addr));
}
__device__ __forceinline__ void ldm_x4_t(uint32_t* r, uint32_t addr) {
    asm volatile("ldmatrix.sync.aligned.m8n8.x4.trans.shared.b16 {%0,%1,%2,%3}, [%4];"
                 : "=r"(r[0]), "=r"(r[1]), "=r"(r[2]), "=r"(r[3]) : "r"(addr));
}
__device__ __forceinline__ void mma16816(float* d, const uint32_t* a, const uint32_t* b) {
    asm volatile(
        "mma.sync.aligned.m16n8k16.row.col.f32.bf16.bf16.f32 "
        "{%0,%1,%2,%3}, {%4,%5,%6,%7}, {%8,%9}, {%0,%1,%2,%3};"
        : "+f"(d[0]), "+f"(d[1]), "+f"(d[2]), "+f"(d[3])
        : "r"(a[0]), "r"(a[1]), "r"(a[2]), "r"(a[3]), "r"(b[0]), "r"(b[1]));
}

#define SWZ(o) ((o) ^ (((o) >> 3) & 0x70))

__device__ __forceinline__ void split2(float v, bf16& hi, bf16& lo) {
    hi = __float2bfloat16(v);
    lo = __float2bfloat16(v - __bfloat162float(hi));
}
__device__ __forceinline__ void splitpack(float p0, float p1, uint32_t& hiw, uint32_t& low) {
    bf16 h0 = __float2bfloat16(p0), h1 = __float2bfloat16(p1);
    float l0 = p0 - __bfloat162float(h0);
    float l1 = p1 - __bfloat162float(h1);
    __nv_bfloat162 hv; hv.x = h0; hv.y = h1;
    __nv_bfloat162 lv; lv.x = __float2bfloat16(l0); lv.y = __float2bfloat16(l1);
    hiw = *(uint32_t*)&hv; low = *(uint32_t*)&lv;
}

// ============================ split-precision mma.sync GEMM ============================
// C[M,N] = (Ahi+Alo)[M,K] @ (Bhi+Blo)[N,K]^T; CTA tile 128 x TN, warp 64 x (TN/4), KC=64.
// modes: 1 split bf16(+bias); 3 bias+gelu->split; 4 (+bias)+resid->fp32
template<int TN>
__global__ void __launch_bounds__(256)
gemmw_kernel(const bf16* __restrict__ Ahi, const bf16* __restrict__ Alo, int lda,
             const bf16* __restrict__ Bhi, const bf16* __restrict__ Blo, int ldb,
             const float* __restrict__ bias,
             const float* __restrict__ resid, int ldr,
             void* outHi, void* outLo, int ldc,
             int K, int mode) {
    constexpr int ABYTES = 128 * 128;
    constexpr int BBYTES = TN * 128;
    constexpr int STAGE  = 2 * ABYTES + 2 * BBYTES;
    constexpr int WN = TN / 4;
    constexpr int NJ = WN / 16;

    extern __shared__ char smem[];
    uint32_t sb = smem_u32(smem);

    int tid = threadIdx.x;
    int wid = tid >> 5, lane = tid & 31;
    int wm = wid >> 2, wn = wid & 3;
    int sub = lane >> 3, r = lane & 7;

    int m0 = blockIdx.y * 128;
    int n0 = blockIdx.x * TN;

    float acc[4][NJ * 2][4];
#pragma unroll
    for (int i = 0; i < 4; i++)
#pragma unroll
        for (int j = 0; j < NJ * 2; j++)
#pragma unroll
            for (int t = 0; t < 4; t++) acc[i][j][t] = 0.f;

    const int nIter = K / 64;

    auto load_stage = [&](int it, int s) {
        int k0 = it * 64;
        uint32_t AhB = sb + s * STAGE;
        uint32_t AlB = AhB + ABYTES;
        uint32_t BhB = AlB + ABYTES;
        uint32_t BlB = BhB + BBYTES;
#pragma unroll
        for (int t = 0; t < 4; t++) {
            int idx = tid + t * 256;
            int row = idx >> 3, seg = idx & 7;
            size_t go = (size_t)(m0 + row) * lda + k0 + seg * 8;
            uint32_t so = SWZ(row * 128 + seg * 16);
            cpasync16(AhB + so, Ahi + go);
            cpasync16(AlB + so, Alo + go);
        }
        constexpr int BT = (TN * 8) / 256;
#pragma unroll
        for (int t = 0; t < BT; t++) {
            int idx = tid + t * 256;
            int row = idx >> 3, seg = idx & 7;
            size_t go = (size_t)(n0 + row) * ldb + k0 + seg * 8;
            uint32_t so = SWZ(row * 128 + seg * 16);
            cpasync16(BhB + so, Bhi + go);
            cpasync16(BlB + so, Blo + go);
        }
        CP_COMMIT();
    };

    load_stage(0, 0);

    for (int it = 0; it < nIter; it++) {
        int s = it & 1;
        CP_WAIT0();
        __syncthreads();                       // single barrier per iter
        if (it + 1 < nIter) load_stage(it + 1, s ^ 1);

        uint32_t AhB = sb + s * STAGE;
        uint32_t AlB = AhB + ABYTES;
        uint32_t BhB = AlB + ABYTES;
        uint32_t BlB = BhB + BBYTES;

#pragma unroll
        for (int ks = 0; ks < 4; ks++) {
            uint32_t ah[4][4], al[4][4];
#pragma unroll
            for (int mi = 0; mi < 4; mi++) {
                int row = wm * 64 + mi * 16 + (sub & 1) * 8 + r;
                int kb  = ks * 32 + (sub >> 1) * 16;
                uint32_t so = SWZ(row * 128 + kb);
                ldm_x4(ah[mi], AhB + so);
                ldm_x4(al[mi], AlB + so);
            }
#pragma unroll
            for (int j = 0; j < NJ; j++) {
                uint32_t bh[4], bl[4];
                int nrow = wn * WN + j * 16 + (sub >> 1) * 8 + r;
                int kb   = ks * 32 + (sub & 1) * 16;
                uint32_t so = SWZ(nrow * 128 + kb);
                ldm_x4(bh, BhB + so);
                ldm_x4(bl, BlB + so);
#pragma unroll
                for (int mi = 0; mi < 4; mi++)
#pragma unroll
                    for (int s2 = 0; s2 < 2; s2++) {
                        float* c = acc[mi][j * 2 + s2];
                        mma16816(c, ah[mi], &bh[s2 * 2]);
                        mma16816(c, ah[mi], &bl[s2 * 2]);
                        mma16816(c, al[mi], &bh[s2 * 2]);
                    }
            }
        }
    }

    int qr = lane >> 2;
    int qc = (lane & 3) * 2;
#pragma unroll
    for (int mi = 0; mi < 4; mi++) {
#pragma unroll
        for (int jj = 0; jj < NJ * 2; jj++) {
            int cg = n0 + wn * WN + (jj >> 1) * 16 + (jj & 1) * 8 + qc;
#pragma unroll
            for (int rr = 0; rr < 2; rr++) {
                int rg = m0 + wm * 64 + mi * 16 + qr + rr * 8;
                float c0 = acc[mi][jj][rr * 2 + 0];
                float c1 = acc[mi][jj][rr * 2 + 1];
                if (bias) { c0 += bias[cg]; c1 += bias[cg + 1]; }
                if (mode == 4) {
                    c0 += resid[(size_t)rg * ldr + cg];
                    c1 += resid[(size_t)rg * ldr + cg + 1];
                    float* o = (float*)outHi;
                    *(float2*)&o[(size_t)rg * ldc + cg] = make_float2(c0, c1);
                } else {
                    if (mode == 3) {
                        c0 = 0.5f * c0 * (1.0f + erff(c0 * 0.70710678118654752f));
                        c1 = 0.5f * c1 * (1.0f + erff(c1 * 0.70710678118654752f));
                    }
                    bf16* ohi = (bf16*)outHi;
                    bf16* olo = (bf16*)outLo;
                    bf16 h0, l0, h1, l1;
                    split2(c0, h0, l0); split2(c1, h1, l1);
                    __nv_bfloat162 hv; hv.x = h0; hv.y = h1;
                    __nv_bfloat162 lv; lv.x = l0; lv.y = l1;
                    *(__nv_bfloat162*)&ohi[(size_t)rg * ldc + cg] = hv;
                    *(__nv_bfloat162*)&olo[(size_t)rg * ldc + cg] = lv;
                }
            }
        }
    }
}

// ============================ fused flash attention ============================
// qkv packed [tok,3072]: q cols 0..1023, k 1024..2047, v 2048..3071 (head = 64 cols).
__global__ void __launch_bounds__(256)
fattn_kernel(const bf16* __restrict__ qkvhi, const bf16* __restrict__ qkvlo,
             const float* __restrict__ x, float* __restrict__ attn) {
    constexpr int BUF = 128 * 128;   // 128 rows x 128B
    constexpr int LD  = 3 * EMB;
    extern __shared__ char smem[];
    uint32_t sb = smem_u32(smem);
    const uint32_t QHb = sb, QLb = sb + BUF;
    const uint32_t ST0 = sb + 2 * BUF;   // + s*4*BUF : KH,KL,VH,VL

    int tid = threadIdx.x, wid = tid >> 5, lane = tid & 31;
    int sub = lane >> 3, r = lane & 7;
    int z = blockIdx.y, zb = z >> 4, zh = z & 15;
    int m0 = blockIdx.x * 128;

    const size_t rowbase = (size_t)zb * SEQ;
    const int qcol = zh * DH, kcol = EMB + zh * DH, vcol = 2 * EMB + zh * DH;

    // Q tile load
#pragma unroll
    for (int t = 0; t < 4; t++) {
        int idx = tid + t * 256;
        int row = idx >> 3, seg = idx & 7;
        size_t go = (rowbase + m0 + row) * LD + qcol + seg * 8;
        uint32_t so = SWZ(row * 128 + seg * 16);
        cpasync16(QHb + so, qkvhi + go);
        cpasync16(QLb + so, qkvlo + go);
    }
    auto load_kv = [&](int j, int s) {
        uint32_t base = ST0 + s * 4 * BUF;
        int k0 = j * 128;
#pragma unroll
        for (int t = 0; t < 4; t++) {
            int idx = tid + t * 256;
            int row = idx >> 3, seg = idx & 7;
            size_t gk = (rowbase + k0 + row) * LD + kcol + seg * 8;
            size_t gv = (rowbase + k0 + row) * LD + vcol + seg * 8;
            uint32_t so = SWZ(row * 128 + seg * 16);
            cpasync16(base + 0 * BUF + so, qkvhi + gk);
            cpasync16(base + 1 * BUF + so, qkvlo + gk);
            cpasync16(base + 2 * BUF + so, qkvhi + gv);
            cpasync16(base + 3 * BUF + so, qkvlo + gv);
        }
        CP_COMMIT();
    };
    CP_COMMIT();          // Q group
    load_kv(0, 0);

    uint32_t qh[4][4], ql[4][4];
    float mr0 = -1e30f, mr1 = -1e30f, lr0 = 0.f, lr1 = 0.f;
    float oacc[8][4];
#pragma unroll
    for (int d = 0; d < 8; d++)
#pragma unroll
        for (int t = 0; t < 4; t++) oacc[d][t] = 0.f;

    for (int j = 0; j < SEQ / 128; j++) {
        int s = j & 1;
        CP_WAIT0();
        __syncthreads();
        if (j == 0) {
#pragma unroll
            for (int ks = 0; ks < 4; ks++) {
                int row = wid * 16 + (sub & 1) * 8 + r;
                int kb  = ks * 32 + (sub >> 1) * 16;
                uint32_t so = SWZ(row * 128 + kb);
                ldm_x4(qh[ks], QHb + so);
                ldm_x4(ql[ks], QLb + so);
            }
        }
        if (j + 1 < SEQ / 128) load_kv(j + 1, s ^ 1);

        uint32_t KHb = ST0 + s * 4 * BUF;
        uint32_t KLb = KHb + BUF, VHb = KLb + BUF, VLb = VHb + BUF;

        // ---- S = Q K^T ----
        float sacc[16][4];
#pragma unroll
        for (int g = 0; g < 16; g++)
#pragma unroll
            for (int t = 0; t < 4; t++) sacc[g][t] = 0.f;

#pragma unroll
        for (int ks = 0; ks < 4; ks++) {
#pragma unroll
            for (int g = 0; g < 8; g++) {
                uint32_t bh[4], bl[4];
                int nrow = g * 16 + (sub >> 1) * 8 + r;
                int kb   = ks * 32 + (sub & 1) * 16;
                uint32_t so = SWZ(nrow * 128 + kb);
                ldm_x4(bh, KHb + so);
                ldm_x4(bl, KLb + so);
#pragma unroll
                for (int s2 = 0; s2 < 2; s2++) {
                    float* c = sacc[g * 2 + s2];
                    mma16816(c, qh[ks], &bh[s2 * 2]);
                    mma16816(c, qh[ks], &bl[s2 * 2]);
                    mma16816(c, ql[ks], &bh[s2 * 2]);
                }
            }
        }

        // ---- online softmax ----
        float mx0 = -1e30f, mx1 = -1e30f;
#pragma unroll
        for (int g = 0; g < 16; g++) {
            mx0 = fmaxf(mx0, fmaxf(sacc[g][0], sacc[g][1]));
            mx1 = fmaxf(mx1, fmaxf(sacc[g][2], sacc[g][3]));
        }
        mx0 = fmaxf(mx0, __shfl_xor_sync(0xFFFFFFFFu, mx0, 1));
        mx0 = fmaxf(mx0, __shfl_xor_sync(0xFFFFFFFFu, mx0, 2));
        mx1 = fmaxf(mx1, __shfl_xor_sync(0xFFFFFFFFu, mx1, 1));
        mx1 = fmaxf(mx1, __shfl_xor_sync(0xFFFFFFFFu, mx1, 2));

        float mn0 = fmaxf(mr0, mx0), mn1 = fmaxf(mr1, mx1);
        float a0 = __expf(mr0 - mn0), a1 = __expf(mr1 - mn1);
        mr0 = mn0; mr1 = mn1;

        float sum0 = 0.f, sum1 = 0.f;
#pragma unroll
        for (int g = 0; g < 16; g++) {
            sacc[g][0] = __expf(sacc[g][0] - mn0);
            sacc[g][1] = __expf(sacc[g][1] - mn0);
            sacc[g][2] = __expf(sacc[g][2] - mn1);
            sacc[g][3] = __expf(sacc[g][3] - mn1);
            sum0 += sacc[g][0] + sacc[g][1];
            sum1 += sacc[g][2] + sacc[g][3];
        }
        sum0 += __shfl_xor_sync(0xFFFFFFFFu, sum0, 1);
        sum0 += __shfl_xor_sync(0xFFFFFFFFu, sum0, 2);
        sum1 += __shfl_xor_sync(0xFFFFFFFFu, sum1, 1);
        sum1 += __shfl_xor_sync(0xFFFFFFFFu, sum1, 2);
        lr0 = lr0 * a0 + sum0;
        lr1 = lr1 * a1 + sum1;
#pragma unroll
        for (int d = 0; d < 8; d++) {
            oacc[d][0] *= a0; oacc[d][1] *= a0;
            oacc[d][2] *= a1; oacc[d][3] *= a1;
        }

        // ---- O += P V ----
#pragma unroll
        for (int t = 0; t < 8; t++) {
            uint32_t pah[4], pal[4];
            splitpack(sacc[2 * t][0],     sacc[2 * t][1],     pah[0], pal[0]);
            splitpack(sacc[2 * t][2],     sacc[2 * t][3],     pah[1], pal[1]);
            splitpack(sacc[2 * t + 1][0], sacc[2 * t + 1][1], pah[2], pal[2]);
            splitpack(sacc[2 * t + 1][2], sacc[2 * t + 1][3], pah[3], pal[3]);
#pragma unroll
            for (int gd = 0; gd < 4; gd++) {
                uint32_t vh4[4], vl4[4];
                int krow = t * 16 + (sub & 1) * 8 + r;
                int nb   = gd * 32 + (sub >> 1) * 16;
                uint32_t so = SWZ(krow * 128 + nb);
                ldm_x4_t(vh4, VHb + so);
                ldm_x4_t(vl4, VLb + so);
#pragma unroll
                for (int s2 = 0; s2 < 2; s2++) {
                    float* o = oacc[gd * 2 + s2];
                    mma16816(o, pah, &vh4[s2 * 2]);
                    mma16816(o, pah, &vl4[s2 * 2]);
                    mma16816(o, pal, &vh4[s2 * 2]);
                }
            }
        }
    }

    // ---- epilogue: O/l + x -> attn (fp32) ----
    float li0 = 1.f / lr0, li1 = 1.f / lr1;
    int qr = lane >> 2, qc = (lane & 3) * 2;
    size_t row0 = rowbase + m0 + wid * 16 + qr;
    size_t row1 = row0 + 8;
#pragma unroll
    for (int gd = 0; gd < 8; gd++) {
        int cg = zh * DH + gd * 8 + qc;
        float2 xr0 = *(const float2*)&x[row0 * EMB + cg];
        float2 xr1 = *(const float2*)&x[row1 * EMB + cg];
        float2 o0 = make_float2(oacc[gd][0] * li0 + xr0.x, oacc[gd][1] * li0 + xr0.y);
        float2 o1 = make_float2(oacc[gd][2] * li1 + xr1.x, oacc[gd][3] * li1 + xr1.y);
        *(float2*)&attn[row0 * EMB + cg] = o0;
        *(float2*)&attn[row1 * EMB + cg] = o1;
    }
}

// ============================ LayerNorm + split ============================
__global__ void ln_split_kernel(const float* __restrict__ x,
                                const float* __restrict__ gamma,
                                const float* __restrict__ beta,
                                bf16* __restrict__ ohi, bf16* __restrict__ olo) {
    int row = blockIdx.x;
    const float* xr = x + (size_t)row * EMB;
    int tid = threadIdx.x;
    float v[4];
    float s = 0.f, s2 = 0.f;
#pragma unroll
    for (int i = 0; i < 4; i++) {
        float t = xr[tid + i * 256];
        v[i] = t; s += t; s2 += t * t;
    }
#pragma unroll
    for (int o = 16; o > 0; o >>= 1) {
        s  += __shfl_down_sync(0xFFFFFFFFu, s,  o);
        s2 += __shfl_down_sync(0xFFFFFFFFu, s2, o);
    }
    __shared__ float rs[8], rs2[8], mu_s, rstd_s;
    int wid = tid >> 5, lane = tid & 31;
    if (lane == 0) { rs[wid] = s; rs2[wid] = s2; }
    __syncthreads();
    if (wid == 0) {
        float a  = (lane < 8) ? rs[lane]  : 0.f;
        float a2 = (lane < 8) ? rs2[lane] : 0.f;
#pragma unroll
        for (int o = 4; o > 0; o >>= 1) {
            a  += __shfl_down_sync(0xFFFFFFFFu, a,  o);
            a2 += __shfl_down_sync(0xFFFFFFFFu, a2, o);
        }
        if (lane == 0) {
            float mu = a * (1.0f / EMB);
            mu_s = mu;
            rstd_s = rsqrtf(a2 * (1.0f / EMB) - mu * mu + 1e-6f);
        }
    }
    __syncthreads();
    float mu = mu_s, rstd = rstd_s;
#pragma unroll
    for (int i = 0; i < 4; i++) {
        int c = tid + i * 256;
        float val = (v[i] - mu) * rstd * gamma[c] + beta[c];
        bf16 h_, l_; split2(val, h_, l_);
        ohi[(size_t)row * EMB + c] = h_;
        olo[(size_t)row * EMB + c] = l_;
    }
}

// ============================ combined weight prep ============================
// One launch: transpose+split Wq/Wk/Wv (into packed [3072,1024]), W1, W2; pack qkv bias.
__global__ void prep_kernel(const float* __restrict__ Wq, const float* __restrict__ Wk,
                            const float* __restrict__ Wv, const float* __restrict__ W1,
                            const float* __restrict__ W2,
                            const float* __restrict__ bq, const float* __restrict__ bk,
                            const float* __restrict__ bv,
                            bf16* __restrict__ wqkvhi, bf16* __restrict__ wqkvlo,
                            bf16* __restrict__ w1hi, bf16* __restrict__ w1lo,
                            bf16* __restrict__ w2hi, bf16* __restrict__ w2lo,
                            float* __restrict__ bqkv) {
    int bid = blockIdx.x;
    int tx = threadIdx.x, ty = threadIdx.y;
    int tid = ty * 32 + tx;

    if (bid == 0) {
        for (int i = tid; i < EMB; i += 256) {
            bqkv[i]           = bq[i];
            bqkv[EMB + i]     = bk[i];
            bqkv[2 * EMB + i] = bv[i];
        }
    }

    const float* W; bf16 *Thi, *Tlo; int K, N, nx, ky;
    if (bid < 3072) {
        int w = bid >> 10, t = bid & 1023;
        W = (w == 0) ? Wq : (w == 1) ? Wk : Wv;
        Thi = wqkvhi + (size_t)w * EMB * EMB;
        Tlo = wqkvlo + (size_t)w * EMB * EMB;
        K = EMB; N = EMB; nx = t & 31; ky = t >> 5;
    } else if (bid < 7168) {
        int t = bid - 3072;
        W = W1; Thi = w1hi; Tlo = w1lo;
        K = EMB; N = DFF; nx = t & 127; ky = t >> 7;
    } else {
        int t = bid - 7168;
        W = W2; Thi = w2hi; Tlo = w2lo;
        K = DFF; N = EMB; nx = t & 31; ky = t >> 5;
    }
    int n0 = nx * 32, k0 = ky * 32;

    __shared__ float tbuf[32][33];
#pragma unroll
    for (int i = ty; i < 32; i += 8)
        tbuf[i][tx] = W[(size_t)(k0 + i) * N + n0 + tx];
    __syncthreads();
#pragma unroll
    for (int i = ty; i < 32; i += 8) {
        float v = tbuf[tx][i];   // = W[k0+tx][n0+i]
        bf16 h_, l_; split2(v, h_, l_);
        size_t oi = (size_t)(n0 + i) * K + k0 + tx;
        Thi[oi] = h_; Tlo[oi] = l_;
    }
}

// ============================ launch ============================
extern "C" void kernel_launch(void* const* d_in, const int* in_sizes, int n_in,
                              void* d_out, int out_size) {
    const float* x   = (const float*)d_in[0];
    const float* Wq  = (const float*)d_in[1];
    const float* bq  = (const float*)d_in[2];
    const float* Wk  = (const float*)d_in[3];
    const float* bk  = (const float*)d_in[4];
    const float* Wv  = (const float*)d_in[5];
    const float* bv  = (const float*)d_in[6];
    const float* g1  = (const float*)d_in[7];
    const float* be1 = (const float*)d_in[8];
    const float* g2  = (const float*)d_in[9];
    const float* be2 = (const float*)d_in[10];
    const float* W1  = (const float*)d_in[11];
    const float* b1  = (const float*)d_in[12];
    const float* W2  = (const float*)d_in[13];
    const float* b2  = (const float*)d_in[14];
    float* out = (float*)d_out;

    bf16 *hhi, *hlo, *wqkvhi, *wqkvlo, *w1hi, *w1lo, *w2hi, *w2lo;
    bf16 *qkvhi, *qkvlo, *h2hi, *h2lo, *ffhi, *fflo;
    float *attn, *bqkv;
    cudaGetSymbolAddress((void**)&hhi,    g_hhi);    cudaGetSymbolAddress((void**)&hlo,    g_hlo);
    cudaGetSymbolAddress((void**)&wqkvhi, g_wqkvhi); cudaGetSymbolAddress((void**)&wqkvlo, g_wqkvlo);
    cudaGetSymbolAddress((void**)&w1hi,   g_w1hi);   cudaGetSymbolAddress((void**)&w1lo,   g_w1lo);
    cudaGetSymbolAddress((void**)&w2hi,   g_w2hi);   cudaGetSymbolAddress((void**)&w2lo,   g_w2lo);
    cudaGetSymbolAddress((void**)&qkvhi,  g_qkvhi);  cudaGetSymbolAddress((void**)&qkvlo,  g_qkvlo);
    cudaGetSymbolAddress((void**)&attn,   g_attn);
    cudaGetSymbolAddress((void**)&h2hi,   g_h2hi);   cudaGetSymbolAddress((void**)&h2lo,   g_h2lo);
    cudaGetSymbolAddress((void**)&ffhi,   g_ffhi);   cudaGetSymbolAddress((void**)&fflo,   g_fflo);
    cudaGetSymbolAddress((void**)&bqkv,   g_bqkv);

    const int SMEM_G = 2 * (2 * 128 * 128 + 2 * 256 * 128);   // 196608 (TN=256)
    const int SMEM_F = 10 * 16384;                             // 163840
    cudaFuncSetAttribute(gemmw_kernel<256>, cudaFuncAttributeMaxDynamicSharedMemorySize, SMEM_G);
    cudaFuncSetAttribute(fattn_kernel, cudaFuncAttributeMaxDynamicSharedMemorySize, SMEM_F);

    // 0) weight prep (all transposes + splits + bias pack) — one launch
    prep_kernel<<<11264, dim3(32, 8)>>>(Wq, Wk, Wv, W1, W2, bq, bk, bv,
                                        wqkvhi, wqkvlo, w1hi, w1lo, w2hi, w2lo, bqkv);

    // 1) LN1
    ln_split_kernel<<<TOK, 256>>>(x, g1, be1, hhi, hlo);

    // 2) fused QKV projection: [4096,3072] = h @ Wqkv^T + bqkv -> packed qkv (split)
    {
        dim3 grid(3 * EMB / 256, TOK / 128);
        gemmw_kernel<256><<<grid, 256, SMEM_G>>>(hhi, hlo, EMB, wqkvhi, wqkvlo, EMB,
                                                 bqkv, nullptr, 0,
                                                 qkvhi, qkvlo, 3 * EMB, EMB, 1);
    }

    // 3) fused attention (+ residual x) -> attn
    {
        dim3 grid(SEQ / 128, BATCH * HEADS);
        fattn_kernel<<<grid, 256, SMEM_F>>>(qkvhi, qkvlo, x, attn);
    }

    // 4) LN2
    ln_split_kernel<<<TOK, 256>>>(attn, g2, be2, h2hi, h2lo);

    // 5) FFN1 (+bias, gelu) -> split
    {
        dim3 grid(DFF / 256, TOK / 128);
        gemmw_kernel<256><<<grid, 256, SMEM_G>>>(h2hi, h2lo, EMB, w1hi, w1lo, EMB,
                                                 b1, nullptr, 0, ffhi, fflo, DFF, EMB, 3);
    }

    // 6) FFN2 (+bias, +attn residual) -> d_out
    {
        dim3 grid(EMB / 256, TOK / 128);
        gemmw_kernel<256><<<grid, 256, SMEM_G>>>(ffhi, fflo, DFF, w2hi, w2lo, DFF,
                                                 b2, attn, EMB, out, nullptr, EMB, DFF, 4);
    }
}